// round 15
// baseline (speedup 1.0000x reference)
#include <cuda_runtime.h>
#include <math.h>
#include <stdint.h>

#define NN    10000
#define NE    120000
#define IND   128
#define HDIM  256
#define H1    8
#define H2    1
#define D2    32

// ---------------- scratch (device globals; no allocations) ----------------
__device__ float    g_hh0  [NN*HDIM];
__device__ float    g_feat1[NN*HDIM];
__device__ float    g_rst1 [NN*HDIM];
__device__ float    g_el1  [NN*H1];
__device__ float    g_er1  [NN*H1];
__device__ float    g_feat2[NN*D2];
__device__ float    g_rst2 [NN*D2];
__device__ float    g_el2  [NN];
__device__ float    g_er2  [NN];
// fused weight W_emb@fc1 and bias b_emb@fc1
__device__ float    g_wcomb[IND*HDIM];
__device__ float    g_bcomb[HDIM];
// BN accumulators packed: [sum1(256) | sq1(256) | sum2(32) | sq2(32)]
__device__ float    g_bnacc[2*HDIM + 2*D2];
// CSR by destination (stores SRC node ids)
__device__ int      g_deg   [NN];
__device__ int      g_rowptr[NN+1];
__device__ int      g_cursor[NN];
__device__ int      g_esrc  [NE];

// ---------------- tf32 helpers ----------------
__device__ __forceinline__ uint32_t f2tf32(float f) {
    uint32_t u;
    asm("cvt.rna.tf32.f32 %0, %1;" : "=r"(u) : "f"(f));
    return u;
}

__device__ __forceinline__ void mma_tf32(float* d, const uint32_t* a, const uint32_t* b) {
    asm volatile(
        "mma.sync.aligned.m16n8k8.row.col.f32.tf32.tf32.f32 "
        "{%0,%1,%2,%3}, {%4,%5,%6,%7}, {%8,%9}, {%0,%1,%2,%3};\n"
        : "+f"(d[0]), "+f"(d[1]), "+f"(d[2]), "+f"(d[3])
        : "r"(a[0]), "r"(a[1]), "r"(a[2]), "r"(a[3]), "r"(b[0]), "r"(b[1]));
}

__device__ __forceinline__ float elu1(float y) { return (y > 0.f) ? y : expm1f(y); }

// ---------------- fp32 prep: W_comb = W_emb @ fc1, b_comb = b_emb @ fc1 ----------------
__global__ void prep_wcomb(const float* __restrict__ W_emb, const float* __restrict__ b_emb,
                           const float* __restrict__ fc1,
                           float* __restrict__ W_comb, float* __restrict__ b_comb) {
    __shared__ float s_sh[HDIM];
    int n = threadIdx.x;           // 0..255
    int k = blockIdx.x;            // 0..128 (row 128 computes the bias)
    const float* s = (k < IND) ? (W_emb + (long)k*HDIM) : b_emb;
    s_sh[n] = s[n];
    __syncthreads();
    float acc[8];
    #pragma unroll
    for (int u = 0; u < 8; u++) acc[u] = 0.f;
    #pragma unroll
    for (int j0 = 0; j0 < HDIM; j0 += 8) {
        #pragma unroll
        for (int u = 0; u < 8; u++)
            acc[u] = fmaf(s_sh[j0 + u], fc1[(long)(j0 + u)*HDIM + n], acc[u]);
    }
    float a = ((acc[0]+acc[1])+(acc[2]+acc[3])) + ((acc[4]+acc[5])+(acc[6]+acc[7]));
    if (k < IND) W_comb[(long)k*HDIM + n] = a;
    else         b_comb[n] = a;
}

// ---------------- tf32 tensor-core GEMM, double-buffered ----------------
// C[M,N] = A'[M,K] @ B[K,N] (+bias)
// FUSE_BN: A'[i,c] = HH0[i,c] + elu(A[i,c]*scale[c] + shift[c]); per-channel
//          (scale,shift) computed in-block from (bnsum,bnsq,bng,bnb).
// ATTN=1: 8-head attention coeffs (WN==32); ATTN=2: 1-head (BN=32, WN=16)
template<int BM, int BN, int BK, int WM, int WN, bool BIAS, bool FUSE_BN, int ATTN>
__global__ __launch_bounds__(256)
void mma_gemm(int M, int N, int K,
              const float* __restrict__ A,
              const float* __restrict__ B,
              const float* __restrict__ bias,
              const float* __restrict__ HH0,
              const float* __restrict__ bnsum,
              const float* __restrict__ bnsq,
              const float* __restrict__ bng,
              const float* __restrict__ bnb,
              const float* __restrict__ wl_g,
              const float* __restrict__ wr_g,
              float* __restrict__ el_out,
              float* __restrict__ er_out,
              float* __restrict__ C) {
    constexpr int WARPS_N = BN / WN;
    constexpr int FM = WM / 16;
    constexpr int FN = WN / 8;
    constexpr int AV = BM * BK / (4 * 256);
    constexpr int BV = BK * BN / (4 * 256);
    constexpr int AC = BK / 4;
    constexpr int BC = BN / 4;
    constexpr int APAD = BK + 4;
    constexpr int BPAD = BN + 8;
    constexpr int ASZ = BM * APAD;
    constexpr int BSZ = BK * BPAD;

    extern __shared__ __align__(16) uint32_t sm[];
    uint32_t* AsB = sm;
    uint32_t* BsB = sm + 2 * ASZ;
    __shared__ float attn_el[64][2], attn_er[64][2];          // ATTN==2 only
    __shared__ float s_bns[FUSE_BN ? HDIM : 1], s_bnt[FUSE_BN ? HDIM : 1];

    const int tid  = threadIdx.x;
    const int wid  = tid >> 5;
    const int lane = tid & 31;
    const int g    = lane >> 2;
    const int tig  = lane & 3;
    const int wm   = (wid / WARPS_N) * WM;
    const int wn   = (wid % WARPS_N) * WN;
    const int bm0  = blockIdx.y * BM;
    const int bn0  = blockIdx.x * BN;

    if (FUSE_BN) {
        for (int c = tid; c < K; c += 256) {
            float inv_n = 1.f / (float)M;
            float mu  = bnsum[c] * inv_n;
            float var = bnsq[c] * inv_n - mu*mu;
            float sc  = bng[c] * rsqrtf(var + 1e-5f);
            s_bns[c] = sc;
            s_bnt[c] = bnb[c] - mu * sc;
        }
        __syncthreads();
    }

    float acc[FM][FN][4];
    #pragma unroll
    for (int i = 0; i < FM; i++)
        #pragma unroll
        for (int j = 0; j < FN; j++)
            #pragma unroll
            for (int r = 0; r < 4; r++) acc[i][j][r] = 0.f;

    float4 aR[AV], bR[BV];

    auto loadA = [&](int k0) {
        #pragma unroll
        for (int i = 0; i < AV; i++) {
            int v = tid + i * 256;
            int r = v / AC, c4 = (v % AC) * 4;
            int gr = bm0 + r;
            float4 x = make_float4(0.f, 0.f, 0.f, 0.f);
            if (gr < M) {
                x = *(const float4*)&A[(long)gr * K + k0 + c4];
                if (FUSE_BN) {
                    int c = k0 + c4;
                    float4 hv = *(const float4*)&HH0[(long)gr * K + c];
                    x.x = hv.x + elu1(x.x * s_bns[c    ] + s_bnt[c    ]);
                    x.y = hv.y + elu1(x.y * s_bns[c + 1] + s_bnt[c + 1]);
                    x.z = hv.z + elu1(x.z * s_bns[c + 2] + s_bnt[c + 2]);
                    x.w = hv.w + elu1(x.w * s_bns[c + 3] + s_bnt[c + 3]);
                }
            }
            aR[i] = x;
        }
    };
    auto loadB = [&](int k0) {
        #pragma unroll
        for (int i = 0; i < BV; i++) {
            int v = tid + i * 256;
            int r = v / BC, c4 = (v % BC) * 4;
            bR[i] = *(const float4*)&B[(long)(k0 + r) * N + bn0 + c4];
        }
    };
    auto stsA = [&](int buf) {
        #pragma unroll
        for (int i = 0; i < AV; i++) {
            int v = tid + i * 256;
            int r = v / AC, c4 = (v % AC) * 4;
            uint4 u;
            u.x = f2tf32(aR[i].x); u.y = f2tf32(aR[i].y);
            u.z = f2tf32(aR[i].z); u.w = f2tf32(aR[i].w);
            *(uint4*)&AsB[buf * ASZ + r * APAD + c4] = u;
        }
    };
    auto stsB = [&](int buf) {
        #pragma unroll
        for (int i = 0; i < BV; i++) {
            int v = tid + i * 256;
            int r = v / BC, c4 = (v % BC) * 4;
            uint4 u;
            u.x = f2tf32(bR[i].x); u.y = f2tf32(bR[i].y);
            u.z = f2tf32(bR[i].z); u.w = f2tf32(bR[i].w);
            *(uint4*)&BsB[buf * BSZ + r * BPAD + c4] = u;
        }
    };

    loadA(0);
    loadB(0);
    stsA(0);
    stsB(0);
    __syncthreads();

    const int KT = K / BK;
    for (int kt = 0; kt < KT; kt++) {
        int cur = kt & 1;
        if (kt + 1 < KT) {
            loadA((kt + 1) * BK);
            loadB((kt + 1) * BK);
        }
        const uint32_t* Asc = AsB + cur * ASZ;
        const uint32_t* Bsc = BsB + cur * BSZ;
        #pragma unroll
        for (int k8 = 0; k8 < BK; k8 += 8) {
            uint32_t af[FM][4], bf[FN][2];
            #pragma unroll
            for (int fm = 0; fm < FM; fm++) {
                int m = wm + fm * 16 + g;
                af[fm][0] = Asc[m * APAD + k8 + tig];
                af[fm][1] = Asc[(m + 8) * APAD + k8 + tig];
                af[fm][2] = Asc[m * APAD + k8 + tig + 4];
                af[fm][3] = Asc[(m + 8) * APAD + k8 + tig + 4];
            }
            #pragma unroll
            for (int fn = 0; fn < FN; fn++) {
                int n = wn + fn * 8 + g;
                bf[fn][0] = Bsc[(k8 + tig) * BPAD + n];
                bf[fn][1] = Bsc[(k8 + tig + 4) * BPAD + n];
            }
            #pragma unroll
            for (int fm = 0; fm < FM; fm++)
                #pragma unroll
                for (int fn = 0; fn < FN; fn++)
                    mma_tf32(acc[fm][fn], af[fm], bf[fn]);
        }
        if (kt + 1 < KT) {
            stsA(cur ^ 1);
            stsB(cur ^ 1);
            __syncthreads();
        }
    }

    #pragma unroll
    for (int fm = 0; fm < FM; fm++) {
        int r0 = bm0 + wm + fm * 16 + g;
        #pragma unroll
        for (int fn = 0; fn < FN; fn++) {
            int cb = bn0 + wn + fn * 8 + 2 * tig;
            if (BIAS) {
                float bx = bias[cb], by = bias[cb + 1];
                acc[fm][fn][0] += bx; acc[fm][fn][1] += by;
                acc[fm][fn][2] += bx; acc[fm][fn][3] += by;
            }
            if (r0 < M)
                *(float2*)&C[(long)r0 * N + cb] =
                    make_float2(acc[fm][fn][0], acc[fm][fn][1]);
            if (r0 + 8 < M)
                *(float2*)&C[(long)(r0 + 8) * N + cb] =
                    make_float2(acc[fm][fn][2], acc[fm][fn][3]);
        }
    }

    if (ATTN == 1) {
        int h = (bn0 + wn) >> 5;   // WN == 32: one head per warp
        float wlv[FN][2], wrv[FN][2];
        #pragma unroll
        for (int fn = 0; fn < FN; fn++) {
            int d = fn * 8 + 2 * tig;
            wlv[fn][0] = wl_g[h * 32 + d];  wlv[fn][1] = wl_g[h * 32 + d + 1];
            wrv[fn][0] = wr_g[h * 32 + d];  wrv[fn][1] = wr_g[h * 32 + d + 1];
        }
        #pragma unroll
        for (int fm = 0; fm < FM; fm++) {
            float elA = 0.f, erA = 0.f, elB = 0.f, erB = 0.f;
            #pragma unroll
            for (int fn = 0; fn < FN; fn++) {
                elA += acc[fm][fn][0] * wlv[fn][0] + acc[fm][fn][1] * wlv[fn][1];
                elB += acc[fm][fn][2] * wlv[fn][0] + acc[fm][fn][3] * wlv[fn][1];
                erA += acc[fm][fn][0] * wrv[fn][0] + acc[fm][fn][1] * wrv[fn][1];
                erB += acc[fm][fn][2] * wrv[fn][0] + acc[fm][fn][3] * wrv[fn][1];
            }
            #pragma unroll
            for (int off = 1; off <= 2; off <<= 1) {
                elA += __shfl_xor_sync(0xffffffffu, elA, off);
                elB += __shfl_xor_sync(0xffffffffu, elB, off);
                erA += __shfl_xor_sync(0xffffffffu, erA, off);
                erB += __shfl_xor_sync(0xffffffffu, erB, off);
            }
            int gr = bm0 + wm + fm * 16 + g;
            if (tig == 0) {
                if (gr < M)     { el_out[gr * 8 + h] = elA;       er_out[gr * 8 + h] = erA; }
                if (gr + 8 < M) { el_out[(gr + 8) * 8 + h] = elB; er_out[(gr + 8) * 8 + h] = erB; }
            }
        }
    }
    if (ATTN == 2) {
        float wlv[FN][2], wrv[FN][2];
        #pragma unroll
        for (int fn = 0; fn < FN; fn++) {
            int d = wn + fn * 8 + 2 * tig;
            wlv[fn][0] = wl_g[d];  wlv[fn][1] = wl_g[d + 1];
            wrv[fn][0] = wr_g[d];  wrv[fn][1] = wr_g[d + 1];
        }
        float elA = 0.f, erA = 0.f, elB = 0.f, erB = 0.f;
        #pragma unroll
        for (int fn = 0; fn < FN; fn++) {
            elA += acc[0][fn][0] * wlv[fn][0] + acc[0][fn][1] * wlv[fn][1];
            elB += acc[0][fn][2] * wlv[fn][0] + acc[0][fn][3] * wlv[fn][1];
            erA += acc[0][fn][0] * wrv[fn][0] + acc[0][fn][1] * wrv[fn][1];
            erB += acc[0][fn][2] * wrv[fn][0] + acc[0][fn][3] * wrv[fn][1];
        }
        #pragma unroll
        for (int off = 1; off <= 2; off <<= 1) {
            elA += __shfl_xor_sync(0xffffffffu, elA, off);
            elB += __shfl_xor_sync(0xffffffffu, elB, off);
            erA += __shfl_xor_sync(0xffffffffu, erA, off);
            erB += __shfl_xor_sync(0xffffffffu, erB, off);
        }
        int wcol = wn >> 4;
        if (tig == 0) {
            attn_el[wm + g][wcol]     = elA;  attn_er[wm + g][wcol]     = erA;
            attn_el[wm + 8 + g][wcol] = elB;  attn_er[wm + 8 + g][wcol] = erB;
        }
        __syncthreads();
        if (tid < 64) {
            int gr = bm0 + tid;
            if (gr < M) {
                el_out[gr] = attn_el[tid][0] + attn_el[tid][1];
                er_out[gr] = attn_er[tid][0] + attn_er[tid][1];
            }
        }
    }
}

// ---------------- CSR construction ----------------
__global__ void csr_count(const int* __restrict__ dst, int* __restrict__ deg, int E) {
    int e = blockIdx.x * blockDim.x + threadIdx.x;
    if (e < E) atomicAdd(&deg[dst[e]], 1);
}

__global__ void csr_scan(const int* __restrict__ deg, int* __restrict__ rowptr,
                         int* __restrict__ cursor) {
    __shared__ int part[1024];
    int tid = threadIdx.x;
    const int PER = (NN + 1023) / 1024;  // 10
    int base = tid * PER;
    int local[PER];
    int s = 0;
    #pragma unroll
    for (int i = 0; i < PER; i++) {
        int idx = base + i;
        local[i] = (idx < NN) ? deg[idx] : 0;
        s += local[i];
    }
    part[tid] = s;
    __syncthreads();
    for (int off = 1; off < 1024; off <<= 1) {
        int v = (tid >= off) ? part[tid - off] : 0;
        __syncthreads();
        part[tid] += v;
        __syncthreads();
    }
    int excl = part[tid] - s;
    #pragma unroll
    for (int i = 0; i < PER; i++) {
        int idx = base + i;
        if (idx < NN) { rowptr[idx] = excl; cursor[idx] = excl; }
        excl += local[i];
    }
    if (tid == 1023) rowptr[NN] = excl;
}

__global__ void csr_fill(const int* __restrict__ dst, const int* __restrict__ src,
                         int* __restrict__ cursor, int* __restrict__ esrc, int E) {
    int e = blockIdx.x * blockDim.x + threadIdx.x;
    if (e >= E) return;
    int p = atomicAdd(&cursor[dst[e]], 1);
    esrc[p] = src[e];
}

__device__ __forceinline__ float leaky(float x) { return (x >= 0.f) ? x : 0.2f * x; }

// ---------------- gather aggregation, layer 1 (+ fused BN stats) ----------------
// TWO warps per node: warp half=0 handles heads 0-3, half=1 handles heads 4-7.
__global__ void gat_gather1(const int* __restrict__ rowptr, const int* __restrict__ esrc,
                            const float* __restrict__ el,    // [N,8]
                            const float* __restrict__ er,    // [N,8]
                            const float* __restrict__ feat,  // [N,256]
                            float* __restrict__ rst,
                            float* __restrict__ gsum, float* __restrict__ gsq) {
    __shared__ float bn_s[256], bn_q[256];
    int tid = threadIdx.x;
    bn_s[tid] = 0.f; bn_q[tid] = 0.f;
    __syncthreads();

    int wid  = tid >> 5;
    int lane = tid & 31;
    int node = blockIdx.x * 4 + (wid >> 1);
    int half = wid & 1;
    if (node < NN) {
        int s0 = rowptr[node], deg = rowptr[node+1] - s0;

        float4 erv = *(const float4*)(er + (long)node*8 + half*4);
        float erh[4] = {erv.x, erv.y, erv.z, erv.w};

        float m[4], s[4], acc[4];
        #pragma unroll
        for (int u = 0; u < 4; u++) { m[u] = -3.0e38f; s[u] = 0.f; acc[u] = 0.f; }

        for (int base = 0; base < deg; base += 32) {
            int cnt = min(32, deg - base);
            int sv = 0;
            float l[4];
            #pragma unroll
            for (int u = 0; u < 4; u++) l[u] = -3.0e38f;
            if (lane < cnt) {
                sv = esrc[s0 + base + lane];
                float4 a = *(const float4*)(el + (long)sv*8 + half*4);
                l[0] = leaky(a.x + erh[0]); l[1] = leaky(a.y + erh[1]);
                l[2] = leaky(a.z + erh[2]); l[3] = leaky(a.w + erh[3]);
            }
            float p[4];
            #pragma unroll
            for (int u = 0; u < 4; u++) {
                float cm = l[u];
                #pragma unroll
                for (int off = 16; off; off >>= 1)
                    cm = fmaxf(cm, __shfl_xor_sync(0xffffffffu, cm, off));
                float nm = fmaxf(m[u], cm);
                float r = __expf(m[u] - nm);
                s[u]  *= r;
                acc[u] *= r;
                p[u] = __expf(l[u] - nm);
                float ps = p[u];
                #pragma unroll
                for (int off = 16; off; off >>= 1)
                    ps += __shfl_xor_sync(0xffffffffu, ps, off);
                s[u] += ps;
                m[u] = nm;
            }
            for (int j = 0; j < cnt; j++) {
                int sn = __shfl_sync(0xffffffffu, sv, j);
                const float* fp = feat + (long)sn*HDIM + half*128 + lane;
                #pragma unroll
                for (int u = 0; u < 4; u++) {
                    float a = __shfl_sync(0xffffffffu, p[u], j);
                    acc[u] = fmaf(a, fp[u*32], acc[u]);
                }
            }
        }
        float* rp = rst + (long)node*HDIM + half*128 + lane;
        #pragma unroll
        for (int u = 0; u < 4; u++) {
            float v = acc[u] / (s[u] + 1e-16f);
            rp[u*32] = v;
            atomicAdd(&bn_s[half*128 + u*32 + lane], v);
            atomicAdd(&bn_q[half*128 + u*32 + lane], v*v);
        }
    }
    __syncthreads();
    atomicAdd(&gsum[tid], bn_s[tid]);
    atomicAdd(&gsq[tid],  bn_q[tid]);
}

// ---------------- gather aggregation, layer 2 (+ fused BN stats) ----------------
__global__ void gat_gather2(const int* __restrict__ rowptr, const int* __restrict__ esrc,
                            const float* __restrict__ el,
                            const float* __restrict__ er,
                            const float* __restrict__ feat,  // [N,32]
                            float* __restrict__ rst,
                            float* __restrict__ gsum, float* __restrict__ gsq) {
    __shared__ float bn_s[32], bn_q[32];
    int tid = threadIdx.x;
    if (tid < 32) { bn_s[tid] = 0.f; bn_q[tid] = 0.f; }
    __syncthreads();

    int node = blockIdx.x * (blockDim.x >> 5) + (tid >> 5);
    int lane = tid & 31;
    if (node < NN) {
        int s0 = rowptr[node], deg = rowptr[node+1] - s0;
        float ern = er[node];

        float m = -3.0e38f, s = 0.f, acc = 0.f;
        for (int base = 0; base < deg; base += 32) {
            int cnt = min(32, deg - base);
            int sv = 0;
            float l = -3.0e38f;
            if (lane < cnt) {
                sv = esrc[s0 + base + lane];
                l = leaky(el[sv] + ern);
            }
            float cm = l;
            #pragma unroll
            for (int off = 16; off; off >>= 1)
                cm = fmaxf(cm, __shfl_xor_sync(0xffffffffu, cm, off));
            float nm = fmaxf(m, cm);
            float r = __expf(m - nm);
            s *= r; acc *= r;
            float p = __expf(l - nm);
            float ps = p;
            #pragma unroll
            for (int off = 16; off; off >>= 1)
                ps += __shfl_xor_sync(0xffffffffu, ps, off);
            s += ps;
            m = nm;
            for (int j = 0; j < cnt; j++) {
                int sn = __shfl_sync(0xffffffffu, sv, j);
                float a = __shfl_sync(0xffffffffu, p, j);
                acc = fmaf(a, feat[(long)sn*D2 + lane], acc);
            }
        }
        float v = acc / (s + 1e-16f);
        rst[(long)node*D2 + lane] = v;
        atomicAdd(&bn_s[lane], v);
        atomicAdd(&bn_q[lane], v*v);
    }
    __syncthreads();
    if (tid < 32) {
        atomicAdd(&gsum[tid], bn_s[tid]);
        atomicAdd(&gsq[tid],  bn_q[tid]);
    }
}

// ---------------- BN apply + ELU (layer 2 -> output) ----------------
__global__ void bn_apply(const float* __restrict__ x,
                         const float* __restrict__ gsum, const float* __restrict__ gsq,
                         const float* __restrict__ g, const float* __restrict__ b,
                         float* __restrict__ out, int n, int C) {
    int idx = blockIdx.x * blockDim.x + threadIdx.x;
    if (idx >= n * C) return;
    int c = idx % C;
    float inv_n = 1.f / (float)n;
    float mu  = gsum[c] * inv_n;
    float var = gsq[c] * inv_n - mu*mu;
    float y = g[c] * (x[idx] - mu) * rsqrtf(var + 1e-5f) + b[c];
    out[idx] = elu1(y);
}

// ---------------- host launch ----------------
static inline void* sym(const void* s) {
    void* p = nullptr;
    cudaGetSymbolAddress(&p, s);
    return p;
}

#define SMEM_G12 ((2*64*(32+4) + 2*32*(64+8)) * 4)    // 36864 (BN=64)
#define SMEM_G3  ((2*64*(32+4) + 2*32*(32+8))  * 4)   // 28672

extern "C" void kernel_launch(void* const* d_in, const int* in_sizes, int n_in,
                              void* d_out, int out_size) {
    const float* h     = (const float*)d_in[0];
    const int*   src   = (const int*)  d_in[2];
    const int*   dst   = (const int*)  d_in[3];
    const float* W_emb = (const float*)d_in[4];
    const float* b_emb = (const float*)d_in[5];
    const float* fc1   = (const float*)d_in[18];
    const float* al1   = (const float*)d_in[19];
    const float* ar1   = (const float*)d_in[20];
    const float* g1    = (const float*)d_in[21];
    const float* b1    = (const float*)d_in[22];
    const float* fc2   = (const float*)d_in[23];
    const float* al2   = (const float*)d_in[24];
    const float* ar2   = (const float*)d_in[25];
    const float* g2    = (const float*)d_in[26];
    const float* b2    = (const float*)d_in[27];
    float* out = (float*)d_out;

    float* hh0   = (float*)sym(g_hh0);
    float* feat1 = (float*)sym(g_feat1);
    float* rst1  = (float*)sym(g_rst1);
    float* el1   = (float*)sym(g_el1);
    float* er1   = (float*)sym(g_er1);
    float* feat2 = (float*)sym(g_feat2);
    float* rst2  = (float*)sym(g_rst2);
    float* el2   = (float*)sym(g_el2);
    float* er2   = (float*)sym(g_er2);
    float* wcomb = (float*)sym(g_wcomb);
    float* bcomb = (float*)sym(g_bcomb);
    float* bnacc = (float*)sym(g_bnacc);
    int*   deg   = (int*)  sym(g_deg);
    int*   rowptr= (int*)  sym(g_rowptr);
    int*   cursor= (int*)  sym(g_cursor);
    int*   esrc  = (int*)  sym(g_esrc);

    float* bnsum1 = bnacc;
    float* bnsq1  = bnacc + HDIM;
    float* bnsum2 = bnacc + 2*HDIM;
    float* bnsq2  = bnacc + 2*HDIM + D2;

    // side streams + fork/join events (host resources, created once; no device mem)
    static cudaStream_t s2 = nullptr, s3 = nullptr;
    static cudaEvent_t evFork = nullptr, evCsr = nullptr, evHh0 = nullptr;
    if (!s2) {
        cudaStreamCreateWithFlags(&s2, cudaStreamNonBlocking);
        cudaStreamCreateWithFlags(&s3, cudaStreamNonBlocking);
        cudaEventCreateWithFlags(&evFork, cudaEventDisableTiming);
        cudaEventCreateWithFlags(&evCsr,  cudaEventDisableTiming);
        cudaEventCreateWithFlags(&evHh0,  cudaEventDisableTiming);
    }

    // ---- fork ----
    cudaEventRecord(evFork, 0);
    cudaStreamWaitEvent(s2, evFork, 0);
    cudaStreamWaitEvent(s3, evFork, 0);

    // stream B: CSR
    cudaMemsetAsync(deg, 0, sizeof(int)*NN, s2);
    csr_count<<<(NE + 255)/256, 256, 0, s2>>>(dst, deg, NE);
    csr_scan <<<1, 1024, 0, s2>>>(deg, rowptr, cursor);
    csr_fill <<<(NE + 255)/256, 256, 0, s2>>>(dst, src, cursor, esrc, NE);
    cudaEventRecord(evCsr, s2);

    // stream C: hh0 GEMM (BN=64 tiles for occupancy)
    {
        dim3 grid(HDIM/64, (NN + 63)/64);   // (4, 157)
        mma_gemm<64,64,32,16,32,true,false,0><<<grid, 256, SMEM_G12, s3>>>(
            NN, HDIM, IND, h, W_emb, b_emb,
            nullptr, nullptr, nullptr, nullptr, nullptr,
            nullptr, nullptr, nullptr, nullptr, hh0);
    }
    cudaEventRecord(evHh0, s3);

    // stream A (critical path): prep -> feat1 GEMM (+attn) -> gather1 -> ...
    cudaMemsetAsync(bnacc, 0, sizeof(float)*(2*HDIM + 2*D2));
    prep_wcomb<<<IND + 1, HDIM>>>(W_emb, b_emb, fc1, wcomb, bcomb);
    {
        dim3 grid(HDIM/64, (NN + 63)/64);   // (4, 157)
        mma_gemm<64,64,32,16,32,true,false,1><<<grid, 256, SMEM_G12>>>(
            NN, HDIM, IND, h, wcomb, bcomb,
            nullptr, nullptr, nullptr, nullptr, nullptr,
            al1, ar1, el1, er1, feat1);
    }

    // join 1: CSR ready
    cudaStreamWaitEvent(0, evCsr, 0);
    gat_gather1<<<(NN + 3)/4, 256>>>(rowptr, esrc, el1, er1, feat1, rst1,
                                     bnsum1, bnsq1);

    // join 2: hh0 ready (needed for FUSE_BN residual)
    cudaStreamWaitEvent(0, evHh0, 0);
    {
        dim3 grid(1, (NN + 63)/64);
        mma_gemm<64,32,32,16,16,false,true,2><<<grid, 256, SMEM_G3>>>(
            NN, D2, HDIM, rst1, fc2, nullptr,
            hh0, bnsum1, bnsq1, g1, b1,
            al2, ar2, el2, er2, feat2);
    }
    gat_gather2<<<(NN*32 + 255)/256, 256>>>(rowptr, esrc, el2, er2, feat2, rst2,
                                            bnsum2, bnsq2);
    bn_apply<<<(NN*D2 + 255)/256, 256>>>(rst2, bnsum2, bnsq2, g2, b2, out, NN, D2);

    (void)in_sizes; (void)n_in; (void)out_size;
}

// round 17
// speedup vs baseline: 1.0433x; 1.0433x over previous
#include <cuda_runtime.h>
#include <math.h>
#include <stdint.h>

#define NN    10000
#define NE    120000
#define IND   128
#define HDIM  256
#define H1    8
#define H2    1
#define D2    32
#define G2B   625    // gather2 persistent grid (all co-resident)

// ---------------- scratch (device globals; no allocations) ----------------
__device__ float    g_hh0  [NN*HDIM];
__device__ float    g_feat1[NN*HDIM];
__device__ float    g_rst1 [NN*HDIM];
__device__ float    g_el1  [NN*H1];
__device__ float    g_er1  [NN*H1];
__device__ float    g_feat2[NN*D2];
__device__ float    g_el2  [NN];
__device__ float    g_er2  [NN];
// fused weight W_emb@fc1 and bias b_emb@fc1
__device__ float    g_wcomb[IND*HDIM];
__device__ float    g_bcomb[HDIM];
// BN accumulators packed: [sum1(256) | sq1(256) | sum2(32) | sq2(32)]
__device__ float    g_bnacc[2*HDIM + 2*D2];
__device__ int      g_ctr[1];        // gather2 grid-barrier counter
// CSR by destination (stores SRC node ids)
__device__ int      g_deg   [NN];
__device__ int      g_rowptr[NN+1];
__device__ int      g_cursor[NN];
__device__ int      g_esrc  [NE];

// ---------------- tf32 helpers ----------------
__device__ __forceinline__ uint32_t f2tf32(float f) {
    uint32_t u;
    asm("cvt.rna.tf32.f32 %0, %1;" : "=r"(u) : "f"(f));
    return u;
}

__device__ __forceinline__ void mma_tf32(float* d, const uint32_t* a, const uint32_t* b) {
    asm volatile(
        "mma.sync.aligned.m16n8k8.row.col.f32.tf32.tf32.f32 "
        "{%0,%1,%2,%3}, {%4,%5,%6,%7}, {%8,%9}, {%0,%1,%2,%3};\n"
        : "+f"(d[0]), "+f"(d[1]), "+f"(d[2]), "+f"(d[3])
        : "r"(a[0]), "r"(a[1]), "r"(a[2]), "r"(a[3]), "r"(b[0]), "r"(b[1]));
}

__device__ __forceinline__ float elu1(float y) { return (y > 0.f) ? y : expm1f(y); }

// ---------------- fp32 prep: W_comb = W_emb @ fc1, b_comb = b_emb @ fc1 ----------------
__global__ void prep_wcomb(const float* __restrict__ W_emb, const float* __restrict__ b_emb,
                           const float* __restrict__ fc1,
                           float* __restrict__ W_comb, float* __restrict__ b_comb) {
    __shared__ float s_sh[HDIM];
    int n = threadIdx.x;           // 0..255
    int k = blockIdx.x;            // 0..128 (row 128 computes the bias)
    const float* s = (k < IND) ? (W_emb + (long)k*HDIM) : b_emb;
    s_sh[n] = s[n];
    __syncthreads();
    float acc[8];
    #pragma unroll
    for (int u = 0; u < 8; u++) acc[u] = 0.f;
    #pragma unroll
    for (int j0 = 0; j0 < HDIM; j0 += 8) {
        #pragma unroll
        for (int u = 0; u < 8; u++)
            acc[u] = fmaf(s_sh[j0 + u], fc1[(long)(j0 + u)*HDIM + n], acc[u]);
    }
    float a = ((acc[0]+acc[1])+(acc[2]+acc[3])) + ((acc[4]+acc[5])+(acc[6]+acc[7]));
    if (k < IND) W_comb[(long)k*HDIM + n] = a;
    else         b_comb[n] = a;
}

// ---------------- tf32 tensor-core GEMM, double-buffered ----------------
// C[M,N] = A'[M,K] @ B[K,N] (+bias)
// FUSE_BN: A'[i,c] = HH0[i,c] + elu(A[i,c]*scale[c] + shift[c]); per-channel
//          (scale,shift) computed in-block from (bnsum,bnsq,bng,bnb).
// ATTN=1: 8-head attention coeffs (WN==32); ATTN=2: 1-head (BN=32, WN=16)
template<int BM, int BN, int BK, int WM, int WN, bool BIAS, bool FUSE_BN, int ATTN>
__global__ __launch_bounds__(256)
void mma_gemm(int M, int N, int K,
              const float* __restrict__ A,
              const float* __restrict__ B,
              const float* __restrict__ bias,
              const float* __restrict__ HH0,
              const float* __restrict__ bnsum,
              const float* __restrict__ bnsq,
              const float* __restrict__ bng,
              const float* __restrict__ bnb,
              const float* __restrict__ wl_g,
              const float* __restrict__ wr_g,
              float* __restrict__ el_out,
              float* __restrict__ er_out,
              float* __restrict__ C) {
    constexpr int WARPS_N = BN / WN;
    constexpr int FM = WM / 16;
    constexpr int FN = WN / 8;
    constexpr int AV = BM * BK / (4 * 256);
    constexpr int BV = BK * BN / (4 * 256);
    constexpr int AC = BK / 4;
    constexpr int BC = BN / 4;
    constexpr int APAD = BK + 4;
    constexpr int BPAD = BN + 8;
    constexpr int ASZ = BM * APAD;
    constexpr int BSZ = BK * BPAD;

    extern __shared__ __align__(16) uint32_t sm[];
    uint32_t* AsB = sm;
    uint32_t* BsB = sm + 2 * ASZ;
    __shared__ float attn_el[64][2], attn_er[64][2];          // ATTN==2 only
    __shared__ float s_bns[FUSE_BN ? HDIM : 1], s_bnt[FUSE_BN ? HDIM : 1];

    const int tid  = threadIdx.x;
    const int wid  = tid >> 5;
    const int lane = tid & 31;
    const int g    = lane >> 2;
    const int tig  = lane & 3;
    const int wm   = (wid / WARPS_N) * WM;
    const int wn   = (wid % WARPS_N) * WN;
    const int bm0  = blockIdx.y * BM;
    const int bn0  = blockIdx.x * BN;

    if (FUSE_BN) {
        for (int c = tid; c < K; c += 256) {
            float inv_n = 1.f / (float)M;
            float mu  = bnsum[c] * inv_n;
            float var = bnsq[c] * inv_n - mu*mu;
            float sc  = bng[c] * rsqrtf(var + 1e-5f);
            s_bns[c] = sc;
            s_bnt[c] = bnb[c] - mu * sc;
        }
        __syncthreads();
    }

    float acc[FM][FN][4];
    #pragma unroll
    for (int i = 0; i < FM; i++)
        #pragma unroll
        for (int j = 0; j < FN; j++)
            #pragma unroll
            for (int r = 0; r < 4; r++) acc[i][j][r] = 0.f;

    float4 aR[AV], bR[BV];

    auto loadA = [&](int k0) {
        #pragma unroll
        for (int i = 0; i < AV; i++) {
            int v = tid + i * 256;
            int r = v / AC, c4 = (v % AC) * 4;
            int gr = bm0 + r;
            float4 x = make_float4(0.f, 0.f, 0.f, 0.f);
            if (gr < M) {
                x = *(const float4*)&A[(long)gr * K + k0 + c4];
                if (FUSE_BN) {
                    int c = k0 + c4;
                    float4 hv = *(const float4*)&HH0[(long)gr * K + c];
                    x.x = hv.x + elu1(x.x * s_bns[c    ] + s_bnt[c    ]);
                    x.y = hv.y + elu1(x.y * s_bns[c + 1] + s_bnt[c + 1]);
                    x.z = hv.z + elu1(x.z * s_bns[c + 2] + s_bnt[c + 2]);
                    x.w = hv.w + elu1(x.w * s_bns[c + 3] + s_bnt[c + 3]);
                }
            }
            aR[i] = x;
        }
    };
    auto loadB = [&](int k0) {
        #pragma unroll
        for (int i = 0; i < BV; i++) {
            int v = tid + i * 256;
            int r = v / BC, c4 = (v % BC) * 4;
            bR[i] = *(const float4*)&B[(long)(k0 + r) * N + bn0 + c4];
        }
    };
    auto stsA = [&](int buf) {
        #pragma unroll
        for (int i = 0; i < AV; i++) {
            int v = tid + i * 256;
            int r = v / AC, c4 = (v % AC) * 4;
            uint4 u;
            u.x = f2tf32(aR[i].x); u.y = f2tf32(aR[i].y);
            u.z = f2tf32(aR[i].z); u.w = f2tf32(aR[i].w);
            *(uint4*)&AsB[buf * ASZ + r * APAD + c4] = u;
        }
    };
    auto stsB = [&](int buf) {
        #pragma unroll
        for (int i = 0; i < BV; i++) {
            int v = tid + i * 256;
            int r = v / BC, c4 = (v % BC) * 4;
            uint4 u;
            u.x = f2tf32(bR[i].x); u.y = f2tf32(bR[i].y);
            u.z = f2tf32(bR[i].z); u.w = f2tf32(bR[i].w);
            *(uint4*)&BsB[buf * BSZ + r * BPAD + c4] = u;
        }
    };

    loadA(0);
    loadB(0);
    stsA(0);
    stsB(0);
    __syncthreads();

    const int KT = K / BK;
    for (int kt = 0; kt < KT; kt++) {
        int cur = kt & 1;
        if (kt + 1 < KT) {
            loadA((kt + 1) * BK);
            loadB((kt + 1) * BK);
        }
        const uint32_t* Asc = AsB + cur * ASZ;
        const uint32_t* Bsc = BsB + cur * BSZ;
        #pragma unroll
        for (int k8 = 0; k8 < BK; k8 += 8) {
            uint32_t af[FM][4], bf[FN][2];
            #pragma unroll
            for (int fm = 0; fm < FM; fm++) {
                int m = wm + fm * 16 + g;
                af[fm][0] = Asc[m * APAD + k8 + tig];
                af[fm][1] = Asc[(m + 8) * APAD + k8 + tig];
                af[fm][2] = Asc[m * APAD + k8 + tig + 4];
                af[fm][3] = Asc[(m + 8) * APAD + k8 + tig + 4];
            }
            #pragma unroll
            for (int fn = 0; fn < FN; fn++) {
                int n = wn + fn * 8 + g;
                bf[fn][0] = Bsc[(k8 + tig) * BPAD + n];
                bf[fn][1] = Bsc[(k8 + tig + 4) * BPAD + n];
            }
            #pragma unroll
            for (int fm = 0; fm < FM; fm++)
                #pragma unroll
                for (int fn = 0; fn < FN; fn++)
                    mma_tf32(acc[fm][fn], af[fm], bf[fn]);
        }
        if (kt + 1 < KT) {
            stsA(cur ^ 1);
            stsB(cur ^ 1);
            __syncthreads();
        }
    }

    #pragma unroll
    for (int fm = 0; fm < FM; fm++) {
        int r0 = bm0 + wm + fm * 16 + g;
        #pragma unroll
        for (int fn = 0; fn < FN; fn++) {
            int cb = bn0 + wn + fn * 8 + 2 * tig;
            if (BIAS) {
                float bx = bias[cb], by = bias[cb + 1];
                acc[fm][fn][0] += bx; acc[fm][fn][1] += by;
                acc[fm][fn][2] += bx; acc[fm][fn][3] += by;
            }
            if (r0 < M)
                *(float2*)&C[(long)r0 * N + cb] =
                    make_float2(acc[fm][fn][0], acc[fm][fn][1]);
            if (r0 + 8 < M)
                *(float2*)&C[(long)(r0 + 8) * N + cb] =
                    make_float2(acc[fm][fn][2], acc[fm][fn][3]);
        }
    }

    if (ATTN == 1) {
        int h = (bn0 + wn) >> 5;   // WN == 32: one head per warp
        float wlv[FN][2], wrv[FN][2];
        #pragma unroll
        for (int fn = 0; fn < FN; fn++) {
            int d = fn * 8 + 2 * tig;
            wlv[fn][0] = wl_g[h * 32 + d];  wlv[fn][1] = wl_g[h * 32 + d + 1];
            wrv[fn][0] = wr_g[h * 32 + d];  wrv[fn][1] = wr_g[h * 32 + d + 1];
        }
        #pragma unroll
        for (int fm = 0; fm < FM; fm++) {
            float elA = 0.f, erA = 0.f, elB = 0.f, erB = 0.f;
            #pragma unroll
            for (int fn = 0; fn < FN; fn++) {
                elA += acc[fm][fn][0] * wlv[fn][0] + acc[fm][fn][1] * wlv[fn][1];
                elB += acc[fm][fn][2] * wlv[fn][0] + acc[fm][fn][3] * wlv[fn][1];
                erA += acc[fm][fn][0] * wrv[fn][0] + acc[fm][fn][1] * wrv[fn][1];
                erB += acc[fm][fn][2] * wrv[fn][0] + acc[fm][fn][3] * wrv[fn][1];
            }
            #pragma unroll
            for (int off = 1; off <= 2; off <<= 1) {
                elA += __shfl_xor_sync(0xffffffffu, elA, off);
                elB += __shfl_xor_sync(0xffffffffu, elB, off);
                erA += __shfl_xor_sync(0xffffffffu, erA, off);
                erB += __shfl_xor_sync(0xffffffffu, erB, off);
            }
            int gr = bm0 + wm + fm * 16 + g;
            if (tig == 0) {
                if (gr < M)     { el_out[gr * 8 + h] = elA;       er_out[gr * 8 + h] = erA; }
                if (gr + 8 < M) { el_out[(gr + 8) * 8 + h] = elB; er_out[(gr + 8) * 8 + h] = erB; }
            }
        }
    }
    if (ATTN == 2) {
        float wlv[FN][2], wrv[FN][2];
        #pragma unroll
        for (int fn = 0; fn < FN; fn++) {
            int d = wn + fn * 8 + 2 * tig;
            wlv[fn][0] = wl_g[d];  wlv[fn][1] = wl_g[d + 1];
            wrv[fn][0] = wr_g[d];  wrv[fn][1] = wr_g[d + 1];
        }
        float elA = 0.f, erA = 0.f, elB = 0.f, erB = 0.f;
        #pragma unroll
        for (int fn = 0; fn < FN; fn++) {
            elA += acc[0][fn][0] * wlv[fn][0] + acc[0][fn][1] * wlv[fn][1];
            elB += acc[0][fn][2] * wlv[fn][0] + acc[0][fn][3] * wlv[fn][1];
            erA += acc[0][fn][0] * wrv[fn][0] + acc[0][fn][1] * wrv[fn][1];
            erB += acc[0][fn][2] * wrv[fn][0] + acc[0][fn][3] * wrv[fn][1];
        }
        #pragma unroll
        for (int off = 1; off <= 2; off <<= 1) {
            elA += __shfl_xor_sync(0xffffffffu, elA, off);
            elB += __shfl_xor_sync(0xffffffffu, elB, off);
            erA += __shfl_xor_sync(0xffffffffu, erA, off);
            erB += __shfl_xor_sync(0xffffffffu, erB, off);
        }
        int wcol = wn >> 4;
        if (tig == 0) {
            attn_el[wm + g][wcol]     = elA;  attn_er[wm + g][wcol]     = erA;
            attn_el[wm + 8 + g][wcol] = elB;  attn_er[wm + 8 + g][wcol] = erB;
        }
        __syncthreads();
        if (tid < 64) {
            int gr = bm0 + tid;
            if (gr < M) {
                el_out[gr] = attn_el[tid][0] + attn_el[tid][1];
                er_out[gr] = attn_er[tid][0] + attn_er[tid][1];
            }
        }
    }
}

// ---------------- CSR construction ----------------
__global__ void csr_count(const int* __restrict__ dst, int* __restrict__ deg, int E) {
    int e = blockIdx.x * blockDim.x + threadIdx.x;
    if (e < E) atomicAdd(&deg[dst[e]], 1);
}

__global__ void csr_scan(const int* __restrict__ deg, int* __restrict__ rowptr,
                         int* __restrict__ cursor) {
    __shared__ int part[1024];
    int tid = threadIdx.x;
    const int PER = (NN + 1023) / 1024;  // 10
    int base = tid * PER;
    int local[PER];
    int s = 0;
    #pragma unroll
    for (int i = 0; i < PER; i++) {
        int idx = base + i;
        local[i] = (idx < NN) ? deg[idx] : 0;
        s += local[i];
    }
    part[tid] = s;
    __syncthreads();
    for (int off = 1; off < 1024; off <<= 1) {
        int v = (tid >= off) ? part[tid - off] : 0;
        __syncthreads();
        part[tid] += v;
        __syncthreads();
    }
    int excl = part[tid] - s;
    #pragma unroll
    for (int i = 0; i < PER; i++) {
        int idx = base + i;
        if (idx < NN) { rowptr[idx] = excl; cursor[idx] = excl; }
        excl += local[i];
    }
    if (tid == 1023) rowptr[NN] = excl;
}

__global__ void csr_fill(const int* __restrict__ dst, const int* __restrict__ src,
                         int* __restrict__ cursor, int* __restrict__ esrc, int E) {
    int e = blockIdx.x * blockDim.x + threadIdx.x;
    if (e >= E) return;
    int p = atomicAdd(&cursor[dst[e]], 1);
    esrc[p] = src[e];
}

__device__ __forceinline__ float leaky(float x) { return (x >= 0.f) ? x : 0.2f * x; }

// ---------------- gather aggregation, layer 1 (+ fused BN stats) ----------------
// TWO warps per node: warp half=0 handles heads 0-3, half=1 handles heads 4-7.
__global__ void gat_gather1(const int* __restrict__ rowptr, const int* __restrict__ esrc,
                            const float* __restrict__ el,    // [N,8]
                            const float* __restrict__ er,    // [N,8]
                            const float* __restrict__ feat,  // [N,256]
                            float* __restrict__ rst,
                            float* __restrict__ gsum, float* __restrict__ gsq) {
    __shared__ float bn_s[256], bn_q[256];
    int tid = threadIdx.x;
    bn_s[tid] = 0.f; bn_q[tid] = 0.f;
    __syncthreads();

    int wid  = tid >> 5;
    int lane = tid & 31;
    int node = blockIdx.x * 4 + (wid >> 1);
    int half = wid & 1;
    if (node < NN) {
        int s0 = rowptr[node], deg = rowptr[node+1] - s0;

        float4 erv = *(const float4*)(er + (long)node*8 + half*4);
        float erh[4] = {erv.x, erv.y, erv.z, erv.w};

        float m[4], s[4], acc[4];
        #pragma unroll
        for (int u = 0; u < 4; u++) { m[u] = -3.0e38f; s[u] = 0.f; acc[u] = 0.f; }

        for (int base = 0; base < deg; base += 32) {
            int cnt = min(32, deg - base);
            int sv = 0;
            float l[4];
            #pragma unroll
            for (int u = 0; u < 4; u++) l[u] = -3.0e38f;
            if (lane < cnt) {
                sv = esrc[s0 + base + lane];
                float4 a = *(const float4*)(el + (long)sv*8 + half*4);
                l[0] = leaky(a.x + erh[0]); l[1] = leaky(a.y + erh[1]);
                l[2] = leaky(a.z + erh[2]); l[3] = leaky(a.w + erh[3]);
            }
            float p[4];
            #pragma unroll
            for (int u = 0; u < 4; u++) {
                float cm = l[u];
                #pragma unroll
                for (int off = 16; off; off >>= 1)
                    cm = fmaxf(cm, __shfl_xor_sync(0xffffffffu, cm, off));
                float nm = fmaxf(m[u], cm);
                float r = __expf(m[u] - nm);
                s[u]  *= r;
                acc[u] *= r;
                p[u] = __expf(l[u] - nm);
                float ps = p[u];
                #pragma unroll
                for (int off = 16; off; off >>= 1)
                    ps += __shfl_xor_sync(0xffffffffu, ps, off);
                s[u] += ps;
                m[u] = nm;
            }
            for (int j = 0; j < cnt; j++) {
                int sn = __shfl_sync(0xffffffffu, sv, j);
                const float* fp = feat + (long)sn*HDIM + half*128 + lane;
                #pragma unroll
                for (int u = 0; u < 4; u++) {
                    float a = __shfl_sync(0xffffffffu, p[u], j);
                    acc[u] = fmaf(a, fp[u*32], acc[u]);
                }
            }
        }
        float* rp = rst + (long)node*HDIM + half*128 + lane;
        #pragma unroll
        for (int u = 0; u < 4; u++) {
            float v = acc[u] / (s[u] + 1e-16f);
            rp[u*32] = v;
            atomicAdd(&bn_s[half*128 + u*32 + lane], v);
            atomicAdd(&bn_q[half*128 + u*32 + lane], v*v);
        }
    }
    __syncthreads();
    atomicAdd(&gsum[tid], bn_s[tid]);
    atomicAdd(&gsq[tid],  bn_q[tid]);
}

// ---------------- gather layer 2 + BN stats + grid barrier + BN apply -> out ----------------
// Persistent: G2B blocks, each warp handles 2 nodes (G2B*8*2 = 10000).
__global__ void gat_gather2_fused(const int* __restrict__ rowptr, const int* __restrict__ esrc,
                                  const float* __restrict__ el,
                                  const float* __restrict__ er,
                                  const float* __restrict__ feat,  // [N,32]
                                  const float* __restrict__ g2, const float* __restrict__ b2,
                                  float* __restrict__ gsum, float* __restrict__ gsq,
                                  int* __restrict__ ctr,
                                  float* __restrict__ out) {
    __shared__ float bn_s[32], bn_q[32];
    int tid = threadIdx.x;
    if (tid < 32) { bn_s[tid] = 0.f; bn_q[tid] = 0.f; }
    __syncthreads();

    int wid  = tid >> 5;
    int lane = tid & 31;
    float vsave[2];
    int   nodes[2];

    #pragma unroll
    for (int it = 0; it < 2; it++) {
        int node = it * (G2B * 8) + blockIdx.x * 8 + wid;
        nodes[it] = node;
        float v = 0.f;
        if (node < NN) {
            int s0 = rowptr[node], deg = rowptr[node+1] - s0;
            float ern = er[node];
            float m = -3.0e38f, s = 0.f, acc = 0.f;
            for (int base = 0; base < deg; base += 32) {
                int cnt = min(32, deg - base);
                int sv = 0;
                float l = -3.0e38f;
                if (lane < cnt) {
                    sv = esrc[s0 + base + lane];
                    l = leaky(el[sv] + ern);
                }
                float cm = l;
                #pragma unroll
                for (int off = 16; off; off >>= 1)
                    cm = fmaxf(cm, __shfl_xor_sync(0xffffffffu, cm, off));
                float nm = fmaxf(m, cm);
                float r = __expf(m - nm);
                s *= r; acc *= r;
                float p = __expf(l - nm);
                float ps = p;
                #pragma unroll
                for (int off = 16; off; off >>= 1)
                    ps += __shfl_xor_sync(0xffffffffu, ps, off);
                s += ps;
                m = nm;
                for (int j = 0; j < cnt; j++) {
                    int sn = __shfl_sync(0xffffffffu, sv, j);
                    float a = __shfl_sync(0xffffffffu, p, j);
                    acc = fmaf(a, feat[(long)sn*D2 + lane], acc);
                }
            }
            v = acc / (s + 1e-16f);
            atomicAdd(&bn_s[lane], v);
            atomicAdd(&bn_q[lane], v*v);
        }
        vsave[it] = v;
    }
    __syncthreads();
    if (tid < 32) {
        atomicAdd(&gsum[tid], bn_s[tid]);
        atomicAdd(&gsq[tid],  bn_q[tid]);
    }

    // ---- software grid barrier (all G2B blocks are co-resident) ----
    __threadfence();
    __syncthreads();
    if (tid == 0) {
        atomicAdd(ctr, 1);
        while (*(volatile int*)ctr < G2B) { }
    }
    __syncthreads();

    // ---- BN finalize + apply + ELU, write out directly ----
    float inv_n = 1.f / (float)NN;
    float mu  = gsum[lane] * inv_n;
    float var = gsq[lane] * inv_n - mu*mu;
    float sc  = g2[lane] * rsqrtf(var + 1e-5f);
    float sh  = b2[lane] - mu * sc;
    #pragma unroll
    for (int it = 0; it < 2; it++) {
        if (nodes[it] < NN)
            out[(long)nodes[it]*D2 + lane] = elu1(vsave[it] * sc + sh);
    }
}

// ---------------- host launch ----------------
static inline void* sym(const void* s) {
    void* p = nullptr;
    cudaGetSymbolAddress(&p, s);
    return p;
}

#define SMEM_G12 ((2*64*(32+4) + 2*32*(128+8)) * 4)   // 53248
#define SMEM_G3  ((2*64*(32+4) + 2*32*(32+8))  * 4)   // 28672

extern "C" void kernel_launch(void* const* d_in, const int* in_sizes, int n_in,
                              void* d_out, int out_size) {
    const float* h     = (const float*)d_in[0];
    const int*   src   = (const int*)  d_in[2];
    const int*   dst   = (const int*)  d_in[3];
    const float* W_emb = (const float*)d_in[4];
    const float* b_emb = (const float*)d_in[5];
    const float* fc1   = (const float*)d_in[18];
    const float* al1   = (const float*)d_in[19];
    const float* ar1   = (const float*)d_in[20];
    const float* g1    = (const float*)d_in[21];
    const float* b1    = (const float*)d_in[22];
    const float* fc2   = (const float*)d_in[23];
    const float* al2   = (const float*)d_in[24];
    const float* ar2   = (const float*)d_in[25];
    const float* g2    = (const float*)d_in[26];
    const float* b2    = (const float*)d_in[27];
    float* out = (float*)d_out;

    float* hh0   = (float*)sym(g_hh0);
    float* feat1 = (float*)sym(g_feat1);
    float* rst1  = (float*)sym(g_rst1);
    float* el1   = (float*)sym(g_el1);
    float* er1   = (float*)sym(g_er1);
    float* feat2 = (float*)sym(g_feat2);
    float* el2   = (float*)sym(g_el2);
    float* er2   = (float*)sym(g_er2);
    float* wcomb = (float*)sym(g_wcomb);
    float* bcomb = (float*)sym(g_bcomb);
    float* bnacc = (float*)sym(g_bnacc);
    int*   ctr   = (int*)  sym(g_ctr);
    int*   deg   = (int*)  sym(g_deg);
    int*   rowptr= (int*)  sym(g_rowptr);
    int*   cursor= (int*)  sym(g_cursor);
    int*   esrc  = (int*)  sym(g_esrc);

    float* bnsum1 = bnacc;
    float* bnsq1  = bnacc + HDIM;
    float* bnsum2 = bnacc + 2*HDIM;
    float* bnsq2  = bnacc + 2*HDIM + D2;

    cudaFuncSetAttribute(mma_gemm<64,128,32,32,32,true,false,0>,
                         cudaFuncAttributeMaxDynamicSharedMemorySize, SMEM_G12);
    cudaFuncSetAttribute(mma_gemm<64,128,32,32,32,true,false,1>,
                         cudaFuncAttributeMaxDynamicSharedMemorySize, SMEM_G12);

    // side stream + fork/join events (host resources, created once; no device mem)
    static cudaStream_t s2 = nullptr;
    static cudaEvent_t evFork = nullptr, evCsr = nullptr, evHh0 = nullptr;
    if (!s2) {
        cudaStreamCreateWithFlags(&s2, cudaStreamNonBlocking);
        cudaEventCreateWithFlags(&evFork, cudaEventDisableTiming);
        cudaEventCreateWithFlags(&evCsr,  cudaEventDisableTiming);
        cudaEventCreateWithFlags(&evHh0,  cudaEventDisableTiming);
    }

    // ---- fork ----
    cudaEventRecord(evFork, 0);
    cudaStreamWaitEvent(s2, evFork, 0);

    // stream B (off critical path): CSR, then hh0 GEMM
    cudaMemsetAsync(deg, 0, sizeof(int)*NN, s2);
    csr_count<<<(NE + 255)/256, 256, 0, s2>>>(dst, deg, NE);
    csr_scan <<<1, 1024, 0, s2>>>(deg, rowptr, cursor);
    csr_fill <<<(NE + 255)/256, 256, 0, s2>>>(dst, src, cursor, esrc, NE);
    cudaEventRecord(evCsr, s2);
    {
        dim3 grid(HDIM/128, (NN + 63)/64);   // (2, 157)
        mma_gemm<64,128,32,32,32,true,false,0><<<grid, 256, SMEM_G12, s2>>>(
            NN, HDIM, IND, h, W_emb, b_emb,
            nullptr, nullptr, nullptr, nullptr, nullptr,
            nullptr, nullptr, nullptr, nullptr, hh0);
    }
    cudaEventRecord(evHh0, s2);

    // stream A (critical path): memsets -> prep -> feat1 GEMM (+attn) -> gather1 -> ...
    cudaMemsetAsync(bnacc, 0, sizeof(float)*(2*HDIM + 2*D2));
    cudaMemsetAsync(ctr,   0, sizeof(int));
    prep_wcomb<<<IND + 1, HDIM>>>(W_emb, b_emb, fc1, wcomb, bcomb);
    {
        dim3 grid(HDIM/128, (NN + 63)/64);   // (2, 157)
        mma_gemm<64,128,32,32,32,true,false,1><<<grid, 256, SMEM_G12>>>(
            NN, HDIM, IND, h, wcomb, bcomb,
            nullptr, nullptr, nullptr, nullptr, nullptr,
            al1, ar1, el1, er1, feat1);
    }

    // join 1: CSR ready
    cudaStreamWaitEvent(0, evCsr, 0);
    gat_gather1<<<(NN + 3)/4, 256>>>(rowptr, esrc, el1, er1, feat1, rst1,
                                     bnsum1, bnsq1);

    // join 2: hh0 ready (needed for FUSE_BN residual)
    cudaStreamWaitEvent(0, evHh0, 0);
    {
        dim3 grid(1, (NN + 63)/64);
        mma_gemm<64,32,32,16,16,false,true,2><<<grid, 256, SMEM_G3>>>(
            NN, D2, HDIM, rst1, fc2, nullptr,
            hh0, bnsum1, bnsq1, g1, b1,
            al2, ar2, el2, er2, feat2);
    }
    // gather layer 2 + BN stats + grid barrier + BN apply (writes out directly)
    gat_gather2_fused<<<G2B, 256>>>(rowptr, esrc, el2, er2, feat2, g2, b2,
                                    bnsum2, bnsq2, ctr, out);

    (void)in_sizes; (void)n_in; (void)out_size;
}